// round 8
// baseline (speedup 1.0000x reference)
#include <cuda_runtime.h>
#include <cuda_bf16.h>

// ActionEncoder: out[b] = tanh(b_t + sum_s W_t[:, s*64 + idx[b,s]])
// Collapsed to a 4160-entry float4 lookup table living in SHARED memory:
//   TAB[i0]                  for t=0  (64 entries; i1 irrelevant)
//   TAB[64 + (i0<<6) + i1]   for t=1  (4096 entries)
// Table built once per CTA (persistent single-wave grid), hot loop is
// pure LDG -> LDS.128 -> STG.128 (~12 instrs/pair, no math).

#define MAX_N   64
#define TABN    (MAX_N + MAX_N * MAX_N)      // 4160 entries
#define SMEM_BYTES (TABN * 16)               // 66560 B
#define SMS     148
#define CTAS_PER_SM 2
#define THREADS 512

__device__ __forceinline__ float ftanh(float x) {
    // tanh(x) = (e^{2x}-1)/(e^{2x}+1); branch-free. Used only in prologue.
    float e = __expf(2.0f * x);
    return __fdividef(e - 1.0f, e + 1.0f);
}

__global__ __launch_bounds__(THREADS, CTAS_PER_SM)
void action_encoder_kernel(const int4* __restrict__ idx2,    // [B/2] two (i0,i1) pairs
                           const int2* __restrict__ types2,  // [B/2] two types
                           const float* __restrict__ W0,     // [4,64]
                           const float* __restrict__ b0,     // [4]
                           const float* __restrict__ W1,     // [4,128]
                           const float* __restrict__ b1,     // [4]
                           float4* __restrict__ out,         // [B]
                           int Bpairs) {
    extern __shared__ float4 TAB[];          // [TABN]
    int tid = threadIdx.x;

    // ---- Prologue: build full output table (~4160/512 ≈ 9 entries/thread) ----
    float bb0x = b0[0], bb0y = b0[1], bb0z = b0[2], bb0w = b0[3];
    float bb1x = b1[0], bb1y = b1[1], bb1z = b1[2], bb1w = b1[3];
    for (int e = tid; e < TABN; e += THREADS) {
        float4 v;
        if (e < MAX_N) {                      // t=0: depends on i0 only
            int i0 = e;
            v = make_float4(W0[0*64 + i0] + bb0x,
                            W0[1*64 + i0] + bb0y,
                            W0[2*64 + i0] + bb0z,
                            W0[3*64 + i0] + bb0w);
        } else {                              // t=1: (i0, i1)
            int r  = e - MAX_N;
            int i0 = r >> 6;
            int i1 = r & 63;
            v = make_float4(W1[0*128 + i0] + W1[0*128 + 64 + i1] + bb1x,
                            W1[1*128 + i0] + W1[1*128 + 64 + i1] + bb1y,
                            W1[2*128 + i0] + W1[2*128 + 64 + i1] + bb1z,
                            W1[3*128 + i0] + W1[3*128 + 64 + i1] + bb1w);
        }
        TAB[e] = make_float4(ftanh(v.x), ftanh(v.y), ftanh(v.z), ftanh(v.w));
    }
    __syncthreads();

    // ---- Hot loop: pure lookup. ~12 instrs per pair. ----
    int stride = gridDim.x * THREADS;
    for (int p = blockIdx.x * THREADS + tid; p < Bpairs; p += stride) {
        int4 ix = idx2[p];                    // coalesced 16B: 2 samples' indices
        int2 tt = types2[p];                  // coalesced  8B: 2 types
        int e0 = tt.x ? (MAX_N + (ix.x << 6) + ix.y) : ix.x;   // SEL, no branch
        int e1 = tt.y ? (MAX_N + (ix.z << 6) + ix.w) : ix.z;
        float4 r0 = TAB[e0];                  // LDS.128
        float4 r1 = TAB[e1];
        out[2 * p]     = r0;                  // coalesced STG.128
        out[2 * p + 1] = r1;
    }
}

extern "C" void kernel_launch(void* const* d_in, const int* in_sizes, int n_in,
                              void* d_out, int out_size) {
    // metadata order: action_indecies, action_n_obj, action_types, W0, b0, W1, b1
    const int4*  idx2   = (const int4*) d_in[0];
    const int2*  types2 = (const int2*) d_in[2];
    const float* W0     = (const float*)d_in[3];
    const float* b0     = (const float*)d_in[4];
    const float* W1     = (const float*)d_in[5];
    const float* b1     = (const float*)d_in[6];
    float4* out = (float4*)d_out;

    int B = in_sizes[2];      // 524288 (even)
    int Bpairs = B >> 1;      // 262144

    // Opt in to >48KB dynamic smem (attribute set, not an allocation;
    // idempotent and capture-safe).
    static int attr_set = 0;
    if (!attr_set) {
        cudaFuncSetAttribute(action_encoder_kernel,
                             cudaFuncAttributeMaxDynamicSharedMemorySize,
                             SMEM_BYTES);
        attr_set = 1;
    }

    int blocks = SMS * CTAS_PER_SM;   // 296: single resident wave
    action_encoder_kernel<<<blocks, THREADS, SMEM_BYTES>>>(
        idx2, types2, W0, b0, W1, b1, out, Bpairs);
}

// round 10
// speedup vs baseline: 1.1396x; 1.1396x over previous
#include <cuda_runtime.h>
#include <cuda_bf16.h>

// ActionEncoder: out[b] = tanh(b_t + sum_s W_t[:, s*64 + idx[b,s]])
// Branchless unified smem tables storing DOUBLED contributions (2*(W+b)), so
// tanh(x) = (e^{2x}-1)/(e^{2x}+1) needs no 2* multiply: e = __expf(a+c).
// 4 adjacent samples/thread: 2x int4 idx + 1x int4 types coalesced loads
// (3 LDGs / 4 samples — fewest of any variant), 4 coalesced STG.128.

#define MAX_N 64

__device__ __forceinline__ float4 enc(const float4* Ta, const float4* Tb,
                                      int t, int i0, int i1) {
    int off = t << 6;
    float4 a = Ta[off + i0];   // doubled slot-0 contribution (+2b)
    float4 c = Tb[off + i1];   // doubled slot-1 contribution (0 for t=0)
    // s = 2x already; tanh = (e^s - 1)/(e^s + 1)
    float ex = __expf(a.x + c.x);
    float ey = __expf(a.y + c.y);
    float ez = __expf(a.z + c.z);
    float ew = __expf(a.w + c.w);
    return make_float4(__fdividef(ex - 1.f, ex + 1.f),
                       __fdividef(ey - 1.f, ey + 1.f),
                       __fdividef(ez - 1.f, ez + 1.f),
                       __fdividef(ew - 1.f, ew + 1.f));
}

__global__ __launch_bounds__(256)
void action_encoder_kernel(const int4* __restrict__ idx2,    // [B/2] two (i0,i1) pairs
                           const int4* __restrict__ types4,  // [B/4] four types
                           const float* __restrict__ W0,     // [4,64]
                           const float* __restrict__ b0,     // [4]
                           const float* __restrict__ W1,     // [4,128]
                           const float* __restrict__ b1,     // [4]
                           float4* __restrict__ out,         // [B]
                           int Bquads) {
    __shared__ float4 Ta[2 * MAX_N];
    __shared__ float4 Tb[2 * MAX_N];
    int tid = threadIdx.x;
    if (tid < MAX_N) {
        Ta[tid] = make_float4(2.f * (W0[0*64 + tid] + b0[0]),
                              2.f * (W0[1*64 + tid] + b0[1]),
                              2.f * (W0[2*64 + tid] + b0[2]),
                              2.f * (W0[3*64 + tid] + b0[3]));
        Tb[tid] = make_float4(0.f, 0.f, 0.f, 0.f);
    } else if (tid < 2 * MAX_N) {
        int j = tid - MAX_N;
        Ta[tid] = make_float4(2.f * (W1[0*128 + j] + b1[0]),
                              2.f * (W1[1*128 + j] + b1[1]),
                              2.f * (W1[2*128 + j] + b1[2]),
                              2.f * (W1[3*128 + j] + b1[3]));
        Tb[tid] = make_float4(2.f * W1[0*128 + 64 + j],
                              2.f * W1[1*128 + 64 + j],
                              2.f * W1[2*128 + 64 + j],
                              2.f * W1[3*128 + 64 + j]);
    }
    __syncthreads();

    int q = blockIdx.x * blockDim.x + tid;   // quad index (4 adjacent samples)
    if (q >= Bquads) return;

    // Front-batched, fully coalesced: 2x LDG.128 + 1x LDG.128 per 4 samples.
    int4 ixA = idx2[2 * q];
    int4 ixB = idx2[2 * q + 1];
    int4 tt  = types4[q];

    float4 r0 = enc(Ta, Tb, tt.x, ixA.x, ixA.y);
    float4 r1 = enc(Ta, Tb, tt.y, ixA.z, ixA.w);
    float4 r2 = enc(Ta, Tb, tt.z, ixB.x, ixB.y);
    float4 r3 = enc(Ta, Tb, tt.w, ixB.z, ixB.w);

    out[4 * q]     = r0;
    out[4 * q + 1] = r1;
    out[4 * q + 2] = r2;
    out[4 * q + 3] = r3;
}

extern "C" void kernel_launch(void* const* d_in, const int* in_sizes, int n_in,
                              void* d_out, int out_size) {
    // metadata order: action_indecies, action_n_obj, action_types, W0, b0, W1, b1
    const int4*  idx2   = (const int4*) d_in[0];
    const int4*  types4 = (const int4*) d_in[2];
    const float* W0     = (const float*)d_in[3];
    const float* b0     = (const float*)d_in[4];
    const float* W1     = (const float*)d_in[5];
    const float* b1     = (const float*)d_in[6];
    float4* out = (float4*)d_out;

    int B = in_sizes[2];      // 524288 (divisible by 4)
    int Bquads = B >> 2;      // 131072

    int threads = 256;
    int blocks  = (Bquads + threads - 1) / threads;  // 512
    action_encoder_kernel<<<blocks, threads>>>(idx2, types4, W0, b0, W1, b1,
                                               out, Bquads);
}

// round 11
// speedup vs baseline: 1.2671x; 1.1119x over previous
#include <cuda_runtime.h>
#include <cuda_bf16.h>

// ActionEncoder: out[b] = tanh(b_t + sum_s W_t[:, s*64 + idx[b,s]])
// Best-measured layout (R4): 2 adjacent samples/thread, 1x int4 + 1x int2
// coalesced loads, 2x coalesced STG.128, regs ~25, occ ~73%.
// Tables store DOUBLED contributions 2*(W+b) so tanh(x)=(e^{2x}-1)/(e^{2x}+1)
// needs no 2* multiply: shortest serial chain (LDS -> FADD -> MUFU -> FADDx2 -> RCP-div).

#define MAX_N 64

__device__ __forceinline__ float4 enc(const float4* Ta, const float4* Tb,
                                      int t, int i0, int i1) {
    int off = t << 6;
    float4 a = Ta[off + i0];   // doubled slot-0 contribution (+2b)
    float4 c = Tb[off + i1];   // doubled slot-1 contribution (0 for t=0)
    // s = 2x already; tanh = (e^s - 1)/(e^s + 1)
    float ex = __expf(a.x + c.x);
    float ey = __expf(a.y + c.y);
    float ez = __expf(a.z + c.z);
    float ew = __expf(a.w + c.w);
    return make_float4(__fdividef(ex - 1.f, ex + 1.f),
                       __fdividef(ey - 1.f, ey + 1.f),
                       __fdividef(ez - 1.f, ez + 1.f),
                       __fdividef(ew - 1.f, ew + 1.f));
}

__global__ __launch_bounds__(256)
void action_encoder_kernel(const int4* __restrict__ idx2,    // [B/2] two (i0,i1) pairs
                           const int2* __restrict__ types2,  // [B/2] two types
                           const float* __restrict__ W0,     // [4,64]
                           const float* __restrict__ b0,     // [4]
                           const float* __restrict__ W1,     // [4,128]
                           const float* __restrict__ b1,     // [4]
                           float4* __restrict__ out,         // [B]
                           int Bpairs) {
    __shared__ float4 Ta[2 * MAX_N];  // doubled slot-0 contribution, bias folded
    __shared__ float4 Tb[2 * MAX_N];  // doubled slot-1 contribution, zero for t=0
    int tid = threadIdx.x;
    if (tid < MAX_N) {
        Ta[tid] = make_float4(2.f * (W0[0*64 + tid] + b0[0]),
                              2.f * (W0[1*64 + tid] + b0[1]),
                              2.f * (W0[2*64 + tid] + b0[2]),
                              2.f * (W0[3*64 + tid] + b0[3]));
        Tb[tid] = make_float4(0.f, 0.f, 0.f, 0.f);
    } else if (tid < 2 * MAX_N) {
        int j = tid - MAX_N;
        Ta[tid] = make_float4(2.f * (W1[0*128 + j] + b1[0]),
                              2.f * (W1[1*128 + j] + b1[1]),
                              2.f * (W1[2*128 + j] + b1[2]),
                              2.f * (W1[3*128 + j] + b1[3]));
        Tb[tid] = make_float4(2.f * W1[0*128 + 64 + j],
                              2.f * W1[1*128 + 64 + j],
                              2.f * W1[2*128 + 64 + j],
                              2.f * W1[3*128 + 64 + j]);
    }
    __syncthreads();

    int p = blockIdx.x * blockDim.x + tid;   // pair index
    if (p >= Bpairs) return;

    int4 ix = idx2[p];    // one coalesced 16B load: both samples' indices
    int2 tt = types2[p];  // one coalesced  8B load: both types

    float4 r0 = enc(Ta, Tb, tt.x, ix.x, ix.y);
    float4 r1 = enc(Ta, Tb, tt.y, ix.z, ix.w);

    out[2 * p]     = r0;
    out[2 * p + 1] = r1;
}

extern "C" void kernel_launch(void* const* d_in, const int* in_sizes, int n_in,
                              void* d_out, int out_size) {
    // metadata order: action_indecies, action_n_obj, action_types, W0, b0, W1, b1
    const int4*  idx2   = (const int4*) d_in[0];
    const int2*  types2 = (const int2*) d_in[2];
    const float* W0     = (const float*)d_in[3];
    const float* b0     = (const float*)d_in[4];
    const float* W1     = (const float*)d_in[5];
    const float* b1     = (const float*)d_in[6];
    float4* out = (float4*)d_out;

    int B = in_sizes[2];      // 524288 (even)
    int Bpairs = B >> 1;      // 262144

    int threads = 256;
    int blocks  = (Bpairs + threads - 1) / threads;  // 1024
    action_encoder_kernel<<<blocks, threads>>>(idx2, types2, W0, b0, W1, b1,
                                               out, Bpairs);
}